// round 5
// baseline (speedup 1.0000x reference)
#include <cuda_runtime.h>
#include <cuda_fp16.h>

#define N_T1 168            // dow(7) * sex(2) * month(12)
#define N_T2 744            // time(24) * day(31)
#define N_T3 100            // age
#define NE   (N_T1 + N_T2 + N_T3)   // 1012

// Pre-projected fused tables in fp16, DUPLICATED per entry:
// entry e occupies 128 B: copy A at [e*128, e*128+64)    -> smem banks 0..15
//                         copy B at [e*128+64, e*128+128) -> smem banks 16..31
__device__ uint4 g_projh[NE * 8];   // NE * 128 B

__global__ void precompute_kernel(const float* __restrict__ emb_dow,
                                  const float* __restrict__ emb_time,
                                  const float* __restrict__ emb_sex,
                                  const float* __restrict__ emb_age,
                                  const float* __restrict__ emb_month,
                                  const float* __restrict__ emb_day,
                                  const float* __restrict__ W,
                                  const float* __restrict__ b) {
    int t = blockIdx.x * blockDim.x + threadIdx.x;
    if (t >= NE * 32) return;
    int e = t >> 5;
    int f = t & 31;
    float v = 0.f;
    // W row layout follows concat order: dow[0:4) time[4:8) sex[8:12) age[12:16) month[16:20) day[20:24)
    if (e < N_T1) {
        int d = e / 24, rem = e % 24;
        int s = rem / 12, m = rem % 12;
        #pragma unroll
        for (int j = 0; j < 4; j++) {
            v = fmaf(emb_dow[d * 4 + j],   W[(0 + j) * 32 + f], v);
            v = fmaf(emb_sex[s * 4 + j],   W[(8 + j) * 32 + f], v);
            v = fmaf(emb_month[m * 4 + j], W[(16 + j) * 32 + f], v);
        }
    } else if (e < N_T1 + N_T2) {
        int e2 = e - N_T1;
        int tm = e2 / 31, dy = e2 % 31;
        #pragma unroll
        for (int j = 0; j < 4; j++) {
            v = fmaf(emb_time[tm * 4 + j], W[(4 + j) * 32 + f], v);
            v = fmaf(emb_day[dy * 4 + j],  W[(20 + j) * 32 + f], v);
        }
    } else {
        int a = e - (N_T1 + N_T2);
        v = b[f];
        #pragma unroll
        for (int j = 0; j < 4; j++)
            v = fmaf(emb_age[a * 4 + j], W[(12 + j) * 32 + f], v);
    }
    __half hv = __float2half_rn(v);
    __half* base = reinterpret_cast<__half*>(g_projh) + e * 64;
    base[f]      = hv;   // copy A
    base[32 + f] = hv;   // copy B
}

__global__ __launch_bounds__(1024, 1)
void mf_main_kernel(const int* __restrict__ dow,
                    const int* __restrict__ tim,
                    const int* __restrict__ sex,
                    const int* __restrict__ age,
                    const int* __restrict__ month,
                    const int* __restrict__ day,
                    const int* __restrict__ dest,
                    const float4* __restrict__ item4,
                    float* __restrict__ out,
                    int n) {
    extern __shared__ uint4 sp[];   // NE * 8 uint4 = 129,536 B (duplicated entries)
    for (int i = threadIdx.x; i < NE * 8; i += blockDim.x)
        sp[i] = g_projh[i];
    __syncthreads();

    const char* spb = reinterpret_cast<const char*>(sp);

    const int lane = threadIdx.x & 31;
    const int warp = threadIdx.x >> 5;
    const int sub  = lane & 7;        // position within 8-lane group
    const int grp  = lane >> 3;       // group id 0..3
    // Odd groups read copy B (banks 16..31), even groups copy A (banks 0..15):
    // half-warp LDS phases are deterministically conflict-free.
    const int par  = (grp & 1) * 64 + sub * 8;

    const int warpsTotal = gridDim.x * (blockDim.x >> 5);
    const int gwarp = blockIdx.x * (blockDim.x >> 5) + warp;

    for (int base = gwarp * 32; base < n; base += warpsTotal * 32) {
        // Phase A: coalesced per-lane index loads; pack 3 table indices into one int.
        int r = base + lane;
        int pk = 0, dd = 0;
        if (r < n) {
            int i1 = dow[r] * 24 + sex[r] * 12 + month[r];   // 0..167  (8 bits)
            int t2 = tim[r] * 31 + day[r];                   // 0..743  (10 bits)
            int a3 = age[r];                                 // 0..99   (7 bits)
            pk = i1 | (t2 << 8) | (a3 << 18);
            dd = dest[r];
        }

        // Software-pipelined index broadcast: fetch s=0's indices up front.
        int pks = __shfl_sync(0xffffffffu, pk, grp);
        int dds = __shfl_sync(0xffffffffu, dd, grp);

        // Phase B: 8 sub-iterations; each processes 4 rows with 8 lanes/row.
        #pragma unroll
        for (int s = 0; s < 8; s++) {
            int j1 = pks & 255;
            int j2 = N_T1 + ((pks >> 8) & 1023);
            int j3 = N_T1 + N_T2 + ((pks >> 18) & 127);

            // Longest-latency load first: 8 lanes x 16 B = one 128B item row.
            float4 v = __ldg(item4 + (size_t)dds * 8 + sub);

            // Each lane reads 8 B (4 halves) of its row's entry; conflict-free.
            uint2 A = *reinterpret_cast<const uint2*>(spb + j1 * 128 + par);
            uint2 C = *reinterpret_cast<const uint2*>(spb + j2 * 128 + par);
            uint2 E = *reinterpret_cast<const uint2*>(spb + j3 * 128 + par);

            // Prefetch next iteration's indices (off critical path).
            if (s < 7) {
                pks = __shfl_sync(0xffffffffu, pk, (s + 1) * 4 + grp);
                dds = __shfl_sync(0xffffffffu, dd, (s + 1) * 4 + grp);
            }

            // Sum the three table slices in packed fp16 (4 HADD2).
            __half2 s0 = __hadd2(__hadd2(*reinterpret_cast<const __half2*>(&A.x),
                                         *reinterpret_cast<const __half2*>(&C.x)),
                                 *reinterpret_cast<const __half2*>(&E.x));
            __half2 s1 = __hadd2(__hadd2(*reinterpret_cast<const __half2*>(&A.y),
                                         *reinterpret_cast<const __half2*>(&C.y)),
                                 *reinterpret_cast<const __half2*>(&E.y));

            float2 f0 = __half22float2(s0);
            float2 f1 = __half22float2(s1);

            float p;
            p =           f0.x * v.x;
            p = fmaf(f0.y, v.y, p);
            p = fmaf(f1.x, v.z, p);
            p = fmaf(f1.y, v.w, p);

            // Reduce across the 8-lane group.
            p += __shfl_xor_sync(0xffffffffu, p, 4);
            p += __shfl_xor_sync(0xffffffffu, p, 2);
            p += __shfl_xor_sync(0xffffffffu, p, 1);

            int row = base + s * 4 + grp;
            if (sub == 0 && row < n)
                out[row] = p;
        }
    }
}

extern "C" void kernel_launch(void* const* d_in, const int* in_sizes, int n_in,
                              void* d_out, int out_size) {
    // Input order: dayofweek, time, sex, age, month, day, destination,
    // emb_dow, emb_time, emb_sex, emb_age, emb_month, emb_day, W, b, item_table
    const int* dow   = (const int*)d_in[0];
    const int* tim   = (const int*)d_in[1];
    const int* sex   = (const int*)d_in[2];
    const int* age   = (const int*)d_in[3];
    const int* month = (const int*)d_in[4];
    const int* day   = (const int*)d_in[5];
    const int* dest  = (const int*)d_in[6];
    const float* emb_dow   = (const float*)d_in[7];
    const float* emb_time  = (const float*)d_in[8];
    const float* emb_sex   = (const float*)d_in[9];
    const float* emb_age   = (const float*)d_in[10];
    const float* emb_month = (const float*)d_in[11];
    const float* emb_day   = (const float*)d_in[12];
    const float* W = (const float*)d_in[13];
    const float* b = (const float*)d_in[14];
    const float4* item4 = (const float4*)d_in[15];
    float* out = (float*)d_out;
    int n = in_sizes[0];

    // 1) Build fused pre-projected fp16 tables (1012 x 32, duplicated per entry).
    int pre_threads = NE * 32;
    precompute_kernel<<<(pre_threads + 255) / 256, 256>>>(
        emb_dow, emb_time, emb_sex, emb_age, emb_month, emb_day, W, b);

    // 2) Main gather + dot kernel. 129,536 B dynamic smem -> opt-in required.
    int smem_bytes = NE * 8 * (int)sizeof(uint4);
    cudaFuncSetAttribute(mf_main_kernel,
                         cudaFuncAttributeMaxDynamicSharedMemorySize, smem_bytes);
    mf_main_kernel<<<152, 1024, smem_bytes>>>(
        dow, tim, sex, age, month, day, dest, item4, out, n);
}